// round 2
// baseline (speedup 1.0000x reference)
#include <cuda_runtime.h>
#include <cstdint>

#define KCODES 1024
#define DIM 64
#define N_ROWS 65536
#define CHUNK 128
#define NCHUNK (KCODES / CHUNK)

typedef unsigned long long ull;

// Scratch (no device allocation allowed -> __device__ globals)
__device__ int    g_idx[N_ROWS];
__device__ int    g_counts[KCODES];
__device__ float  g_Esq[KCODES];
__device__ double g_loss;

// Packed fp32x2 ops (sm_100+). FFMA2 doubles fp32 throughput vs scalar FFMA.
#define FMA2(acc, x, y) asm("fma.rn.f32x2 %0, %1, %2, %0;" : "+l"(acc) : "l"(x), "l"(y))
#define ADD2(r, x, y)   asm("add.rn.f32x2 %0, %1, %2;"     : "=l"(r)   : "l"(x), "l"(y))

// ---------------------------------------------------------------------------
// Kernel 1: per-code squared norms + zero the histogram / loss accumulator.
// esq rounding detail: sum in fp32; its absolute error (~1e-11) is far below
// the reference's d-quantization grid (~3.8e-6), so order is immaterial.
// ---------------------------------------------------------------------------
__global__ void prep_kernel(const float* __restrict__ E) {
    int k = blockIdx.x * blockDim.x + threadIdx.x;
    if (k < KCODES) {
        float s = 0.f;
        #pragma unroll
        for (int d = 0; d < DIM; d++) {
            float v = E[k * DIM + d];
            s = fmaf(v, v, s);
        }
        g_Esq[k] = s;
        g_counts[k] = 0;
    }
    if (k == 0) g_loss = 0.0;
}

// ---------------------------------------------------------------------------
// Kernel 2: argmin over codes, bit-mimicking the reference's rounding chain:
//   d = fl( fl(zsq + esq_k) - 2*s_k )
// zsq ~ 40..90 dominates, so d is quantized to ulp(~64) = 3.8e-6 exactly like
// the JAX reference; 2*s is exact (mul by 2), so fma(-2, s, t) reproduces the
// reference's single rounding of (t - 2M) bit-for-bit. Ties (equal quantized
// d) break to the lowest index via strict '<', matching jnp.argmin.
// zsq's own summation order only shifts all d_k of a row by grid-aligned
// amounts -> argmin-neutral.
// ---------------------------------------------------------------------------
__global__ void __launch_bounds__(128, 2)
argmin_kernel(const float* __restrict__ in, const float* __restrict__ E) {
    __shared__ __align__(16) float sE[CHUNK * DIM];
    __shared__ float sEsq[CHUNK];

    const int t = threadIdx.x;
    const int base = blockIdx.x * 256;
    const int n0 = base + t;
    const int n1 = n0 + 128;
    const int b0 = n0 >> 10, p0 = n0 & 1023;
    const int b1 = n1 >> 10, p1 = n1 & 1023;
    const float* z0p = in + b0 * 65536 + p0;
    const float* z1p = in + b1 * 65536 + p1;

    // Load + pack both z vectors into f32x2 registers; accumulate zsq.
    ull zA[32], zB[32];
    float zsq0 = 0.f, zsq1 = 0.f;
    #pragma unroll
    for (int i = 0; i < 32; i++) {
        float a0 = z0p[(2 * i) * 1024];
        float a1 = z0p[(2 * i + 1) * 1024];
        zsq0 = fmaf(a0, a0, zsq0);
        zsq0 = fmaf(a1, a1, zsq0);
        zA[i] = (ull)__float_as_uint(a0) | ((ull)__float_as_uint(a1) << 32);
        float c0 = z1p[(2 * i) * 1024];
        float c1 = z1p[(2 * i + 1) * 1024];
        zsq1 = fmaf(c0, c0, zsq1);
        zsq1 = fmaf(c1, c1, zsq1);
        zB[i] = (ull)__float_as_uint(c0) | ((ull)__float_as_uint(c1) << 32);
    }

    float best0 = 3.4e38f, best1 = 3.4e38f;
    int bi0 = 0, bi1 = 0;

    for (int c = 0; c < NCHUNK; c++) {
        __syncthreads();
        // Stage 128 codes (32 KB) into smem, float4-wide, fully coalesced.
        const float4* src = (const float4*)(E + c * CHUNK * DIM);
        float4* dst = (float4*)sE;
        #pragma unroll
        for (int i = 0; i < 16; i++) dst[t + i * 128] = src[t + i * 128];
        sEsq[t] = g_Esq[c * CHUNK + t];
        __syncthreads();

        for (int k = 0; k < CHUNK; k++) {
            const ulonglong2* e2 = (const ulonglong2*)(sE + k * DIM);
            ull a0 = 0, a1 = 0, b0a = 0, b1a = 0;  // 4 independent FMA chains
            #pragma unroll
            for (int j = 0; j < 16; j++) {
                ulonglong2 ee = e2[j];            // ld.shared.v2.u64 (broadcast)
                FMA2(a0, zA[2 * j],     ee.x);
                FMA2(a1, zA[2 * j + 1], ee.y);
                FMA2(b0a, zB[2 * j],     ee.x);
                FMA2(b1a, zB[2 * j + 1], ee.y);
            }
            ull sa, sb;
            ADD2(sa, a0, a1);
            ADD2(sb, b0a, b1a);
            float s0 = __fadd_rn(__uint_as_float((unsigned)sa),
                                 __uint_as_float((unsigned)(sa >> 32)));
            float s1 = __fadd_rn(__uint_as_float((unsigned)sb),
                                 __uint_as_float((unsigned)(sb >> 32)));
            float esq = sEsq[k];
            // Reference rounding chain: t = fl(zsq + esq); d = fl(t - 2s).
            float t0 = __fadd_rn(zsq0, esq);
            float t1 = __fadd_rn(zsq1, esq);
            float d0 = __fmaf_rn(-2.0f, s0, t0);
            float d1 = __fmaf_rn(-2.0f, s1, t1);
            int kk = c * CHUNK + k;
            if (d0 < best0) { best0 = d0; bi0 = kk; }  // strict < keeps first min
            if (d1 < best1) { best1 = d1; bi1 = kk; }
        }
    }

    g_idx[n0] = bi0;
    g_idx[n1] = bi1;
    atomicAdd(&g_counts[bi0], 1);
    atomicAdd(&g_counts[bi1], 1);
}

// ---------------------------------------------------------------------------
// Kernel 3: gather Zq (straight-through, bit-mimicking fl(z + fl(e - z))),
// write transposed [B,C,H,W], accumulate sum((e - z)^2) for the losses.
// ---------------------------------------------------------------------------
__global__ void gather_kernel(const float* __restrict__ in,
                              const float* __restrict__ E,
                              float* __restrict__ out) {
    const int t = threadIdx.x;
    const int n = blockIdx.x * 256 + t;
    const int b = n >> 10, p = n & 1023;
    const int id = g_idx[n];

    float e[DIM];
    const float4* er = (const float4*)(E + id * DIM);
    #pragma unroll
    for (int i = 0; i < 16; i++) {
        float4 v = er[i];
        e[4 * i] = v.x; e[4 * i + 1] = v.y; e[4 * i + 2] = v.z; e[4 * i + 3] = v.w;
    }

    const float* zp = in + b * 65536 + p;
    float* zq = out + 1 + b * 65536 + p;  // Zq starts at out[1]
    float ls = 0.f;
    #pragma unroll
    for (int d = 0; d < DIM; d++) {
        float z = zp[d * 1024];
        float diff = __fsub_rn(e[d], z);          // ref: Zq_t - Ze_t in fp32
        ls = fmaf(diff, diff, ls);
        zq[d * 1024] = __fadd_rn(z, diff);        // ref: Ze + (Zq - Ze) in fp32
    }

    // Block-reduce loss partial, one double atomic per block.
    ls += __shfl_xor_sync(0xffffffffu, ls, 16);
    ls += __shfl_xor_sync(0xffffffffu, ls, 8);
    ls += __shfl_xor_sync(0xffffffffu, ls, 4);
    ls += __shfl_xor_sync(0xffffffffu, ls, 2);
    ls += __shfl_xor_sync(0xffffffffu, ls, 1);
    __shared__ float warpsum[8];
    if ((t & 31) == 0) warpsum[t >> 5] = ls;
    __syncthreads();
    if (t == 0) {
        float s = 0.f;
        #pragma unroll
        for (int w = 0; w < 8; w++) s += warpsum[w];
        atomicAdd(&g_loss, (double)s);
    }
}

// ---------------------------------------------------------------------------
// Kernel 4: perplexity from histogram + scalar outputs.
// ---------------------------------------------------------------------------
__global__ void finalize_kernel(float* __restrict__ out) {
    __shared__ float red[32];
    const int t = threadIdx.x;  // 1024 threads
    float cnt = (float)g_counts[t];
    float p = cnt * (1.0f / 65536.0f);
    float v = p * log2f(p + 1e-10f);

    v += __shfl_xor_sync(0xffffffffu, v, 16);
    v += __shfl_xor_sync(0xffffffffu, v, 8);
    v += __shfl_xor_sync(0xffffffffu, v, 4);
    v += __shfl_xor_sync(0xffffffffu, v, 2);
    v += __shfl_xor_sync(0xffffffffu, v, 1);
    if ((t & 31) == 0) red[t >> 5] = v;
    __syncthreads();
    if (t < 32) {
        float x = red[t];
        x += __shfl_xor_sync(0xffffffffu, x, 16);
        x += __shfl_xor_sync(0xffffffffu, x, 8);
        x += __shfl_xor_sync(0xffffffffu, x, 4);
        x += __shfl_xor_sync(0xffffffffu, x, 2);
        x += __shfl_xor_sync(0xffffffffu, x, 1);
        if (t == 0) {
            float entropy = -x;
            float perp = exp2f(entropy);
            float l = (float)(g_loss * (1.0 / 4194304.0));  // mean over B*H*W*D
            out[0] = l + 0.25f * l;          // q + BETA*e (q == e numerically)
            out[1 + N_ROWS * DIM]     = l;   // e_latent_loss
            out[1 + N_ROWS * DIM + 1] = l;   // q_latent_loss
            out[1 + N_ROWS * DIM + 2] = perp;
        }
    }
}

// ---------------------------------------------------------------------------
extern "C" void kernel_launch(void* const* d_in, const int* in_sizes, int n_in,
                              void* d_out, int out_size) {
    const float* in = (const float*)d_in[0];
    const float* E  = (const float*)d_in[1];
    float* out = (float*)d_out;

    prep_kernel<<<4, 256>>>(E);
    argmin_kernel<<<256, 128>>>(in, E);
    gather_kernel<<<256, 256>>>(in, E, out);
    finalize_kernel<<<1, 1024>>>(out);
}